// round 2
// baseline (speedup 1.0000x reference)
#include <cuda_runtime.h>
#include <cstdint>

// ---- Problem constants (must match reference exactly) ----
#define GX 432
#define GY 496
#define GZ 1
#define VTOTAL (GX * GY * GZ)      // 214272
#define MAX_VOX 160000
#define NPTS 200000                 // points per batch
#define NBATCH 4
#define P_TOTAL (NPTS * NBATCH)     // 800000
#define CHUNK 1024
#define NCHUNK ((VTOTAL + CHUNK - 1) / CHUNK)  // 210

// low = PC_RANGE[:3], vsz = VOXEL_SIZE (float32 literals, as in reference)
__device__ __constant__ float c_low[3]  = {0.0f, -39.68f, -3.0f};
__device__ __constant__ float c_vsz[3]  = {0.16f, 0.16f, 4.0f};

// ---- Scratch (device globals: no allocations allowed) ----
__device__ float4 g_sums[VTOTAL];
__device__ int    g_counts[VTOTAL];
__device__ int    g_chunkSums[NCHUNK];
__device__ int    g_chunkOff[NCHUNK];

// ============================================================
// K0: zero accumulators + output
// ============================================================
__global__ void k_zero(float4* __restrict__ out4) {
    int i = blockIdx.x * blockDim.x + threadIdx.x;
    if (i < VTOTAL) {
        g_sums[i] = make_float4(0.f, 0.f, 0.f, 0.f);
        g_counts[i] = 0;
    }
    if (i < MAX_VOX) {
        out4[i] = make_float4(0.f, 0.f, 0.f, 0.f);
    }
}

// ============================================================
// K1: scatter-accumulate points into voxel sums/counts
// clouds layout: (B, C, N) feature-major. Point p=(b,n):
//   x = in[b*4N + 0*N + n], y = +1N, z = +2N, w = +3N
// ============================================================
__global__ void k_accum(const float* __restrict__ in) {
    int p = blockIdx.x * blockDim.x + threadIdx.x;
    if (p >= P_TOTAL) return;
    int b = p / NPTS;
    int n = p - b * NPTS;
    const float* base = in + (size_t)b * (4 * NPTS);

    float x = base[n];
    float y = base[NPTS + n];
    float z = base[2 * NPTS + n];
    float w = base[3 * NPTS + n];

    // IEEE-exact: floor((coord - low) / vsz), matching JAX f32 semantics
    float fx = floorf(__fdiv_rn(__fsub_rn(x, c_low[0]), c_vsz[0]));
    float fy = floorf(__fdiv_rn(__fsub_rn(y, c_low[1]), c_vsz[1]));
    float fz = floorf(__fdiv_rn(__fsub_rn(z, c_low[2]), c_vsz[2]));

    int cx = (int)fx, cy = (int)fy, cz = (int)fz;
    bool valid = (cx >= 0) & (cx < GX) & (cy >= 0) & (cy < GY) & (cz >= 0) & (cz < GZ);
    if (!valid) return;

    int lin = (cz * GY + cy) * GX + cx;

    // 128-bit vector reduction (sm_90+) + scalar count reduction
    atomicAdd(&g_sums[lin], make_float4(x, y, z, w));
    atomicAdd(&g_counts[lin], 1);
}

// ============================================================
// K2: per-chunk occupancy counts (1024 threads = 32 warps / block)
// ============================================================
__global__ void k_chunksum() {
    int v = blockIdx.x * CHUNK + threadIdx.x;
    int flag = (v < VTOTAL) && (g_counts[v] > 0);
    unsigned m = __ballot_sync(0xffffffffu, flag);
    __shared__ int ws[32];
    int lane = threadIdx.x & 31;
    int wid  = threadIdx.x >> 5;
    if (lane == 0) ws[wid] = __popc(m);
    __syncthreads();
    if (wid == 0) {
        int s = ws[lane];
        #pragma unroll
        for (int o = 16; o > 0; o >>= 1) s += __shfl_down_sync(0xffffffffu, s, o);
        if (lane == 0) g_chunkSums[blockIdx.x] = s;
    }
}

// ============================================================
// K3: exclusive scan over NCHUNK (=210) chunk sums, one block of 256
// ============================================================
__global__ void k_scan() {
    __shared__ int sh[256];
    int t = threadIdx.x;
    int orig = (t < NCHUNK) ? g_chunkSums[t] : 0;
    int v = orig;
    #pragma unroll
    for (int o = 1; o < 256; o <<= 1) {
        sh[t] = v;
        __syncthreads();
        int add = (t >= o) ? sh[t - o] : 0;
        __syncthreads();
        v += add;
    }
    if (t < NCHUNK) g_chunkOff[t] = v - orig;  // exclusive
}

// ============================================================
// K4: compute seg = global rank of occupied voxel, write mean
// ============================================================
__global__ void k_out(float4* __restrict__ out4) {
    int v = blockIdx.x * CHUNK + threadIdx.x;
    int cnt = (v < VTOTAL) ? g_counts[v] : 0;
    int flag = cnt > 0;
    unsigned m = __ballot_sync(0xffffffffu, flag);
    int lane = threadIdx.x & 31;
    int wid  = threadIdx.x >> 5;
    __shared__ int ws[32];
    if (lane == 0) ws[wid] = __popc(m);
    __syncthreads();
    if (wid == 0) {
        int s = ws[lane];
        int incl = s;
        #pragma unroll
        for (int o = 1; o < 32; o <<= 1) {
            int u = __shfl_up_sync(0xffffffffu, incl, o);
            if (lane >= o) incl += u;
        }
        ws[lane] = incl - s;  // exclusive warp offsets
    }
    __syncthreads();
    if (flag) {
        int local = ws[wid] + __popc(m & ((1u << lane) - 1u));
        int seg = g_chunkOff[blockIdx.x] + local;
        if (seg < MAX_VOX) {
            float4 s4 = g_sums[v];
            float fc = (float)cnt;  // cnt >= 1 here
            out4[seg] = make_float4(__fdiv_rn(s4.x, fc),
                                    __fdiv_rn(s4.y, fc),
                                    __fdiv_rn(s4.z, fc),
                                    __fdiv_rn(s4.w, fc));
        }
    }
}

// ============================================================
extern "C" void kernel_launch(void* const* d_in, const int* in_sizes, int n_in,
                              void* d_out, int out_size) {
    const float* clouds = (const float*)d_in[0];
    float4* out4 = (float4*)d_out;

    int zblocks = (VTOTAL + 255) / 256;          // covers VTOTAL > MAX_VOX
    k_zero<<<zblocks, 256>>>(out4);

    int ablocks = (P_TOTAL + 255) / 256;
    k_accum<<<ablocks, 256>>>(clouds);

    k_chunksum<<<NCHUNK, CHUNK>>>();
    k_scan<<<1, 256>>>();
    k_out<<<NCHUNK, CHUNK>>>(out4);
}